// round 1
// baseline (speedup 1.0000x reference)
#include <cuda_runtime.h>

// out[b,t,w,c] = x[b, t+w-9, c] with zero padding outside [0,T)
// B=32, T=4096, W=19, C=30. Output = 74,649,600 floats = 18,662,400 float4.

#define B_DIM 32
#define T_DIM 4096
#define W_DIM 19
#define C_DIM 30
#define PAD   (W_DIM / 2)

__global__ void overlap_window_kernel(const float* __restrict__ x,
                                      float4* __restrict__ out,
                                      unsigned int n4) {
    unsigned int gid = blockIdx.x * blockDim.x + threadIdx.x;
    if (gid >= n4) return;

    unsigned int idx0 = gid * 4u;
    float v[4];
#pragma unroll
    for (int j = 0; j < 4; j++) {
        unsigned int idx = idx0 + j;
        unsigned int c  = idx % C_DIM;
        unsigned int r  = idx / C_DIM;
        unsigned int w  = r % W_DIM;
        unsigned int r2 = r / W_DIM;
        unsigned int t  = r2 % T_DIM;
        unsigned int b  = r2 / T_DIM;
        int st = (int)t + (int)w - PAD;
        float val = 0.0f;
        if (st >= 0 && st < T_DIM) {
            val = __ldg(x + ((unsigned int)b * T_DIM + (unsigned int)st) * C_DIM + c);
        }
        v[j] = val;
    }
    out[gid] = make_float4(v[0], v[1], v[2], v[3]);
}

extern "C" void kernel_launch(void* const* d_in, const int* in_sizes, int n_in,
                              void* d_out, int out_size) {
    const float* x = (const float*)d_in[0];
    float4* out = (float4*)d_out;
    unsigned int n4 = (unsigned int)(out_size / 4);
    const int threads = 256;
    unsigned int blocks = (n4 + threads - 1) / threads;
    overlap_window_kernel<<<blocks, threads>>>(x, out, n4);
}

// round 3
// speedup vs baseline: 1.5232x; 1.5232x over previous
#include <cuda_runtime.h>

// out[b,t,w,c] = x[b, t+w-9, c], zero-padded in t.  B=32, T=4096, W=19, C=30.
// Identity: out row (b,t) [570 floats] == contiguous x slice starting at
// flat element (b*4096 + t - 9)*30, with pad rows zeroed.
//
// Block = (b, tile of TT=64 t-rows). Stage (TT+18)*30 = 2460 floats of x into
// smem (pad pre-zeroed), then emit TT*570 floats as float4 stores.

#define T_DIM   4096
#define C_DIM   30
#define W_DIM   19
#define ROW     570            // W*C
#define PAD     9
#define TT      64             // t-rows per block (must be even)
#define SROWS   (TT + 2*PAD)   // 82
#define SFLOATS (SROWS * C_DIM) // 2460
#define THREADS 512
#define OUT4_PER_TILE (TT * ROW / 4) // 9120

__global__ __launch_bounds__(THREADS)
void overlap_window_smem_kernel(const float* __restrict__ x,
                                float4* __restrict__ out) {
    __shared__ float s[SFLOATS];

    const int tile   = blockIdx.x;           // 0 .. 32*64-1
    const int tpb    = T_DIM / TT;           // 64 tiles per batch
    const int b      = tile / tpb;
    const int t0     = (tile - b * tpb) * TT;
    const int tid    = threadIdx.x;

    // ---- stage x[(b*4096 + t0 - 9)*30 ... +2460) into smem, zeroing pad ----
    // element i of smem is valid iff 0 <= t0 - 9 + i/30 < 4096
    const int lo = (t0 == 0) ? (PAD * C_DIM) : 0;                 // 270 or 0
    const int hi_raw = (T_DIM - t0 + PAD) * C_DIM;                // (4105-t0)*30
    const int hi = hi_raw < SFLOATS ? hi_raw : SFLOATS;
    const int gbase = (b * T_DIM + t0 - PAD) * C_DIM;             // even
    const float2* __restrict__ x2 = (const float2*)x;
    float2* __restrict__ s2 = (float2*)s;

    #pragma unroll
    for (int k = 0; k < (SFLOATS / 2 + THREADS - 1) / THREADS; k++) {
        int idx2 = tid + k * THREADS;
        if (idx2 < SFLOATS / 2) {
            int i = idx2 * 2;
            float2 v = make_float2(0.0f, 0.0f);
            if (i >= lo && i < hi) {
                v = __ldg(&x2[(gbase >> 1) + idx2]);
            }
            s2[idx2] = v;
        }
    }
    __syncthreads();

    // ---- emit TT*570 floats as float4 stores ----
    // flat tile output element e -> row r = e/570, rem = e - 570r,
    // smem source = r*30 + rem. Second float2 may cross into row r+1.
    float4* __restrict__ out_tile = out + (size_t)(b * T_DIM + t0) * ROW / 4;

    for (int q = tid; q < OUT4_PER_TILE; q += THREADS) {
        int e   = q * 4;
        int r   = e / ROW;                 // magic-div by constant
        int rem = e - r * ROW;             // even, 0..568
        int src = r * C_DIM + rem;         // even -> 8B aligned

        int rem2 = rem + 2;
        int src2 = (rem2 >= ROW) ? (r + 1) * C_DIM : (src + 2);

        float2 a  = *(const float2*)&s[src];
        float2 bb = *(const float2*)&s[src2];
        out_tile[q] = make_float4(a.x, a.y, bb.x, bb.y);
    }
}

extern "C" void kernel_launch(void* const* d_in, const int* in_sizes, int n_in,
                              void* d_out, int out_size) {
    const float* x = (const float*)d_in[0];
    float4* out = (float4*)d_out;
    const int blocks = 32 * (T_DIM / TT);   // 2048
    overlap_window_smem_kernel<<<blocks, THREADS>>>(x, out);
}

// round 4
// speedup vs baseline: 1.7066x; 1.1204x over previous
#include <cuda_runtime.h>

// out[b,t,w,c] = x[b, t+w-9, c], zero-padded in t.  B=32, T=4096, W=19, C=30.
// Identity: out row (b,t) [570 floats] == contiguous x slice starting at
// flat element (b*4096 + t - 9)*30, with pad rows zeroed.
//
// Block = (b, tile of TT=64 t-rows). Stage (TT+18)*30 = 2460 floats of x into
// smem (pad pre-zeroed), then emit TT*570 = 36480 floats = 9120 float4 stores.
// 480 threads * 19 iterations = 9120 exactly -> no bounds checks, full unroll.

#define T_DIM   4096
#define C_DIM   30
#define ROW     570            // W*C
#define PAD     9
#define TT      64             // t-rows per block
#define SROWS   (TT + 2*PAD)   // 82
#define SFLOATS (SROWS * C_DIM) // 2460
#define THREADS 480
#define ITERS   19             // TT*ROW/4 / THREADS = 9120/480

__device__ __forceinline__ void stg_cs_v4(float4* p, float4 v) {
    asm volatile("st.global.cs.v4.f32 [%0], {%1,%2,%3,%4};"
                 :: "l"(p), "f"(v.x), "f"(v.y), "f"(v.z), "f"(v.w) : "memory");
}

__global__ __launch_bounds__(THREADS)
void overlap_window_smem_kernel(const float* __restrict__ x,
                                float4* __restrict__ out) {
    __shared__ float s[SFLOATS];

    const int tile = blockIdx.x;            // 0 .. 2047
    const int tpb  = T_DIM / TT;            // 64 tiles per batch
    const int b    = tile / tpb;
    const int t0   = (tile - b * tpb) * TT;
    const int tid  = threadIdx.x;

    // ---- stage x[(b*4096 + t0 - 9)*30 ... +2460) into smem, zeroing pad ----
    const int lo = (t0 == 0) ? (PAD * C_DIM) : 0;
    const int hi_raw = (T_DIM - t0 + PAD) * C_DIM;
    const int hi = hi_raw < SFLOATS ? hi_raw : SFLOATS;
    const int gbase = (b * T_DIM + t0 - PAD) * C_DIM;  // even
    const float2* __restrict__ x2 = (const float2*)x;
    float2* __restrict__ s2 = (float2*)s;

    #pragma unroll
    for (int k = 0; k < (SFLOATS / 2 + THREADS - 1) / THREADS; k++) {
        int idx2 = tid + k * THREADS;
        if (idx2 < SFLOATS / 2) {
            int i = idx2 * 2;
            float2 v = make_float2(0.0f, 0.0f);
            if (i >= lo && i < hi) {
                v = __ldg(&x2[(gbase >> 1) + idx2]);
            }
            s2[idx2] = v;
        }
    }
    __syncthreads();

    // ---- emit 9120 float4s; e = (tid + k*480)*4 ----
    float4* __restrict__ out_tile = out + (size_t)(b * T_DIM + t0) * (ROW / 4) / 1
                                        + 0;
    // (b*4096+t0)*570/4 is integral since TT even and 570*2 = 1140 div by 4
    out_tile = out + ((size_t)(b * T_DIM + t0) * ROW) / 4;

    #pragma unroll
    for (int k = 0; k < ITERS; k++) {
        int q   = tid + k * THREADS;
        int e   = q * 4;
        int r   = e / ROW;                 // magic-div by constant
        int rem = e - r * ROW;             // even, 0..568
        int src = r * C_DIM + rem;         // even -> 8B aligned

        int src2 = (rem + 2 >= ROW) ? (r + 1) * C_DIM : (src + 2);

        float2 a  = *(const float2*)&s[src];
        float2 bb = *(const float2*)&s[src2];
        stg_cs_v4(&out_tile[q], make_float4(a.x, a.y, bb.x, bb.y));
    }
}

extern "C" void kernel_launch(void* const* d_in, const int* in_sizes, int n_in,
                              void* d_out, int out_size) {
    const float* x = (const float*)d_in[0];
    float4* out = (float4*)d_out;
    const int blocks = 32 * (T_DIM / TT);   // 2048
    overlap_window_smem_kernel<<<blocks, THREADS>>>(x, out);
}

// round 5
// speedup vs baseline: 1.7077x; 1.0007x over previous
#include <cuda_runtime.h>

// out[b,t,w,c] = x[b, t+w-9, c], zero-padded in t.  B=32, T=4096, W=19, C=30.
// Identity: out row (b,t) [570 floats] == contiguous x slice starting at
// flat element (b*4096 + t - 9)*30, with pad rows zeroed.
//
// Block = (b, tile of TT=64 t-rows). Stage (TT+18)*30 = 2460 floats of x into
// smem (pad pre-zeroed), then emit TT*570 = 36480 floats as float2 stores.
// float2 granularity => LDS.64 with 8B lane stride = conflict-free smem reads.
// 480 threads * 38 iterations = 18240 float2 exactly -> no bounds checks.

#define T_DIM   4096
#define C_DIM   30
#define ROW     570             // W*C
#define PAD     9
#define TT      64              // t-rows per block
#define SROWS   (TT + 2*PAD)    // 82
#define SFLOATS (SROWS * C_DIM) // 2460
#define THREADS 480
#define ITERS   38              // TT*ROW/2 / THREADS = 18240/480

__device__ __forceinline__ void stg_cs_v2(float2* p, float2 v) {
    asm volatile("st.global.cs.v2.f32 [%0], {%1,%2};"
                 :: "l"(p), "f"(v.x), "f"(v.y) : "memory");
}

__global__ __launch_bounds__(THREADS)
void overlap_window_smem_kernel(const float* __restrict__ x,
                                float2* __restrict__ out2) {
    __shared__ float s[SFLOATS];

    const int tile = blockIdx.x;            // 0 .. 2047
    const int tpb  = T_DIM / TT;            // 64 tiles per batch
    const int b    = tile / tpb;
    const int t0   = (tile - b * tpb) * TT;
    const int tid  = threadIdx.x;

    // ---- stage x[(b*4096 + t0 - 9)*30 ... +2460) into smem, zeroing pad ----
    const int lo = (t0 == 0) ? (PAD * C_DIM) : 0;
    const int hi_raw = (T_DIM - t0 + PAD) * C_DIM;
    const int hi = hi_raw < SFLOATS ? hi_raw : SFLOATS;
    const int gbase = (b * T_DIM + t0 - PAD) * C_DIM;  // even
    const float2* __restrict__ x2 = (const float2*)x;
    float2* __restrict__ s2 = (float2*)s;

    #pragma unroll
    for (int k = 0; k < (SFLOATS / 2 + THREADS - 1) / THREADS; k++) {
        int idx2 = tid + k * THREADS;
        if (idx2 < SFLOATS / 2) {
            int i = idx2 * 2;
            float2 v = make_float2(0.0f, 0.0f);
            if (i >= lo && i < hi) {
                v = __ldg(&x2[(gbase >> 1) + idx2]);
            }
            s2[idx2] = v;
        }
    }
    __syncthreads();

    // ---- emit 18240 float2s; float2 index q = tid + k*480, element e = 2q ----
    // output row r = e/570, rem = e - 570r (even); smem source = r*30 + rem.
    // e advances by 960 per iter: rem += 390 (mod 570), r += 1 or 2.
    float2* __restrict__ out_tile = out2 + ((size_t)(b * T_DIM + t0) * ROW) / 2;

    int e   = tid * 2;                  // 0..958
    int r   = (e >= ROW) ? 1 : 0;
    int rem = e - r * ROW;

    #pragma unroll
    for (int k = 0; k < ITERS; k++) {
        int src = r * C_DIM + rem;      // even -> 8B aligned
        float2 v = *(const float2*)&s[src];
        stg_cs_v2(&out_tile[tid + k * THREADS], v);

        // advance e += 960
        rem += 960 - ROW;               // += 390
        r   += 1;
        if (rem >= ROW) { rem -= ROW; r += 1; }
    }
}

extern "C" void kernel_launch(void* const* d_in, const int* in_sizes, int n_in,
                              void* d_out, int out_size) {
    const float* x = (const float*)d_in[0];
    float2* out2 = (float2*)d_out;
    const int blocks = 32 * (T_DIM / TT);   // 2048
    overlap_window_smem_kernel<<<blocks, THREADS>>>(x, out2);
}